// round 12
// baseline (speedup 1.0000x reference)
#include <cuda_runtime.h>
#include <cstdint>

// ---------------- problem constants ----------------
#define BB      8
#define HEADS   4
#define NQ      3136
#define NKV     784
#define DH      32
#define CC      128
#define TN      64                 // kv tile (12 full tiles + tail of 16)
#define NFULL   12
#define VSTRIDE 26624              // 13 tiles * 2048 floats per (b,h)
#define QPB64   ((BB * NQ) / 64)   // 392
#define KVB64   ((BB * NKV) / 64)  // 98

typedef unsigned long long u64;

// ---------------- scratch (device globals; no allocation) ----------------
__device__ float g_q [BB * HEADS * NQ  * DH];      // permuted d', tf32, scaled by 32^-.5*log2e
__device__ float g_k [BB * HEADS * NKV * DH];      // permuted d', tf32
__device__ float g_v [BB * HEADS * VSTRIDE];       // sigma-permuted Vp, tf32
__device__ float g_xr[BB * NKV * CC];
__device__ float g_ao[BB * NQ  * CC];

// ---------------- helpers ----------------
__device__ __forceinline__ float to_tf32(float x) {
    float r; asm("cvt.rna.tf32.f32 %0, %1;" : "=f"(r) : "f"(x)); return r;
}
__device__ __forceinline__ float ex2(float x) {
    float r; asm("ex2.approx.f32 %0, %1;" : "=f"(r) : "f"(x)); return r;
}
__device__ __forceinline__ unsigned smem_u32(const void* p) {
    return (unsigned)__cvta_generic_to_shared(p);
}
__device__ __forceinline__ void cp16(unsigned dst, const void* src) {
    asm volatile("cp.async.cg.shared.global [%0], [%1], 16;\n" :: "r"(dst), "l"(src));
}
__device__ __forceinline__ void cp_commit() {
    asm volatile("cp.async.commit_group;\n" ::: "memory");
}
__device__ __forceinline__ void cp_wait0() {
    asm volatile("cp.async.wait_group 0;\n" ::: "memory");
}

// mma.sync m16n8k8 tf32 (base PTX, sm_80+)
__device__ __forceinline__ void mma8(float c[4], float a0, float a1, float a2, float a3,
                                     float b0, float b1) {
    asm volatile(
        "mma.sync.aligned.m16n8k8.row.col.f32.tf32.tf32.f32 "
        "{%0,%1,%2,%3}, {%4,%5,%6,%7}, {%8,%9}, {%0,%1,%2,%3};"
        : "+f"(c[0]), "+f"(c[1]), "+f"(c[2]), "+f"(c[3])
        : "r"(__float_as_uint(a0)), "r"(__float_as_uint(a1)),
          "r"(__float_as_uint(a2)), "r"(__float_as_uint(a3)),
          "r"(__float_as_uint(b0)), "r"(__float_as_uint(b1)));
}

// ---------------- tensor-core projection: Y = X(64x128 tile) @ W + b ------
// CTA = 64 rows x 128 cols, 8 warps (2m x 4n), warp tile 32x32,
// K chunks of 32, register-staged pipeline, XOR-swizzled Ws.
// MODE 0: plain fp32 row-major.   MODE 1: K (head-split, d-permute, tf32)
// MODE 2: Q (K-style + qscale).   MODE 4: V (head-split, sigma-permute, tf32)
template<int MODE>
__device__ __forceinline__ void proj_mma_body64(
    const float* __restrict__ X, const float* __restrict__ W,
    const float* __restrict__ bias, float* __restrict__ Y, int rowb)
{
    __shared__ __align__(16) float Xs[32 * 72];    // [k][m], pad 72
    __shared__ __align__(16) float Ws[32 * 136];   // [k][swz(perm(n))]

    const int tid  = threadIdx.x;
    const int lane = tid & 31, w = tid >> 5;
    const int g = lane >> 2, t = lane & 3;
    const int mw  = (w & 1) * 32;
    const int nwq = (w >> 1) * 32;
    const int w4  = (w >> 1) * 4;

    float o[2][4][4];
#pragma unroll
    for (int mf = 0; mf < 2; mf++)
#pragma unroll
        for (int j = 0; j < 4; j++)
#pragma unroll
            for (int c = 0; c < 4; c++) o[mf][j][c] = 0.f;

    float4 xa[2], wa[4];
    auto load_chunk = [&](int kc) {
#pragma unroll
        for (int i = 0; i < 2; i++) {
            int m = lane + 32 * i;
            xa[i] = *(const float4*)&X[(size_t)(rowb + m) * CC + kc + w * 4];
        }
#pragma unroll
        for (int i = 0; i < 4; i++) {
            int vv = tid + i * 256;
            int kk = vv >> 5, ng = vv & 31;
            wa[i] = *(const float4*)&W[(size_t)(kc + kk) * CC + ng * 4];
        }
    };

    load_chunk(0);
    for (int c = 0; c < 4; c++) {
        // ---- store staged chunk to smem (tf32-rounded) ----
#pragma unroll
        for (int i = 0; i < 2; i++) {
            int m = lane + 32 * i;
            float* d = &Xs[(w * 4) * 72 + m];
            d[0]   = to_tf32(xa[i].x);
            d[72]  = to_tf32(xa[i].y);
            d[144] = to_tf32(xa[i].z);
            d[216] = to_tf32(xa[i].w);
        }
#pragma unroll
        for (int i = 0; i < 4; i++) {
            int vv = tid + i * 256;
            int kk = vv >> 5, n0 = (vv & 31) * 4;
            float vals[4] = {to_tf32(wa[i].x), to_tf32(wa[i].y),
                             to_tf32(wa[i].z), to_tf32(wa[i].w)};
#pragma unroll
            for (int c2 = 0; c2 < 4; c2++) {
                int n = n0 + c2;
                int p = (n & 7) * 16 + (n >> 3);
                int sp = p ^ (((p >> 5) & 3) << 2);
                Ws[kk * 136 + sp] = vals[c2];
            }
        }
        __syncthreads();
        if (c < 3) load_chunk((c + 1) * 32);   // overlap next chunk's LDGs

#pragma unroll
        for (int s = 0; s < 4; s++) {
            const float* xr0 = &Xs[(s * 8 + t) * 72 + mw];
            const float* xr1 = xr0 + 4 * 72;
            float aA0 = xr0[g],      aA1 = xr0[g + 8];
            float aA2 = xr1[g],      aA3 = xr1[g + 8];
            float aB0 = xr0[g + 16], aB1 = xr0[g + 24];
            float aB2 = xr1[g + 16], aB3 = xr1[g + 24];

            int p0 = g * 16 + w4;
            int sp0 = p0 ^ (((p0 >> 5) & 3) << 2);
            const float* wr0 = &Ws[(s * 8 + t) * 136 + sp0];
            const float* wr1 = wr0 + 4 * 136;
            float4 b0 = *(const float4*)wr0;
            float4 b1 = *(const float4*)wr1;
            float bb0[4] = {b0.x, b0.y, b0.z, b0.w};
            float bb1[4] = {b1.x, b1.y, b1.z, b1.w};
#pragma unroll
            for (int j = 0; j < 4; j++) {
                mma8(o[0][j], aA0, aA1, aA2, aA3, bb0[j], bb1[j]);
                mma8(o[1][j], aB0, aB1, aB2, aB3, bb0[j], bb1[j]);
            }
        }
        __syncthreads();
    }

    const float qscale = 0.25503486f;   // 32^-0.5 * log2(e)
#pragma unroll
    for (int j = 0; j < 4; j++) {
        int col = nwq + 8 * j + 2 * t;
        if (MODE == 0) {
            float2 bv = *(const float2*)&bias[col];
#pragma unroll
            for (int mf = 0; mf < 2; mf++) {
                int r0 = rowb + mw + 16 * mf + g;
                *(float2*)&Y[(size_t)r0 * CC + col] =
                    make_float2(o[mf][j][0] + bv.x, o[mf][j][1] + bv.y);
                *(float2*)&Y[(size_t)(r0 + 8) * CC + col] =
                    make_float2(o[mf][j][2] + bv.x, o[mf][j][3] + bv.y);
            }
        } else {
            int h = col >> 5;
            int d0 = col & 31, d1 = d0 + 1;
            float bx = bias[col], by = bias[col + 1];
#pragma unroll
            for (int mf = 0; mf < 2; mf++) {
#pragma unroll
                for (int rh = 0; rh < 2; rh++) {
                    int row = rowb + mw + 16 * mf + g + 8 * rh;
                    float v0 = o[mf][j][2 * rh]     + bx;
                    float v1 = o[mf][j][2 * rh + 1] + by;
                    if (MODE == 2) { v0 *= qscale; v1 *= qscale; }
                    if (MODE == 4) {
                        int b = row / NKV, n = row % NKV;
                        int tile = n >> 6, rr = n & 63;
                        int off = ((rr & 7) >> 1) * 512 + 2 * (rr >> 3) + (rr & 1);
                        float* bp = &Y[(size_t)(b * HEADS + h) * VSTRIDE
                                       + tile * 2048 + off];
                        bp[d0 * 16] = to_tf32(v0);
                        bp[d1 * 16] = to_tf32(v1);
                    } else {
                        const int RPB = (MODE == 2) ? NQ : NKV;
                        int b = row / RPB, n = row % RPB;
                        int dp0 = (d0 & 3) * 8 + (d0 >> 2);
                        int dp1 = (d1 & 3) * 8 + (d1 >> 2);
                        float* bp = &Y[((size_t)(b * HEADS + h) * RPB + n) * DH];
                        bp[dp0] = to_tf32(v0);
                        bp[dp1] = to_tf32(v1);
                    }
                }
            }
        }
    }
}

// fused: q projection (tensor) + spatial-reduction conv
__global__ __launch_bounds__(256, 2) void qproj_conv_kernel(
    const float* __restrict__ x,
    const float* __restrict__ Wq, const float* __restrict__ bq, float* __restrict__ Q,
    const float* __restrict__ cw, const float* __restrict__ cb,
    const float* __restrict__ gamma, const float* __restrict__ beta,
    const float* __restrict__ mean, const float* __restrict__ var,
    float* __restrict__ xr)
{
    if (blockIdx.x < QPB64) {
        proj_mma_body64<2>(x, Wq, bq, Q, blockIdx.x * 64);
        return;
    }
    int t = (blockIdx.x - QPB64) * 256 + threadIdx.x;
    if (t >= BB * NKV * CC) return;
    int c = t & (CC - 1);
    int p = (t >> 7) % NKV;
    int b = t / (NKV * CC);
    int oy = p / 28, ox = p % 28;

    const float* xb = x + (size_t)b * NQ * CC;
    float s = 0.f;
#pragma unroll
    for (int i = 0; i < 2; i++)
#pragma unroll
        for (int j = 0; j < 2; j++)
            s += xb[(size_t)((2 * oy + i) * 56 + (2 * ox + j)) * CC + c] * cw[c * 4 + i * 2 + j];
    s += cb[c];
    float iv = gamma[c] * rsqrtf(var[c] + 1e-5f);
    xr[t] = s * iv + (beta[c] - mean[c] * iv);
}

// fused k+v projections (tensor mma)
__global__ __launch_bounds__(256, 2) void kvproj_kernel(
    const float* __restrict__ X,
    const float* __restrict__ Wk, const float* __restrict__ bk, float* __restrict__ K,
    const float* __restrict__ Wv, const float* __restrict__ bv, float* __restrict__ V)
{
    if (blockIdx.x < KVB64)
        proj_mma_body64<1>(X, Wk, bk, K, blockIdx.x * 64);
    else
        proj_mma_body64<4>(X, Wv, bv, V, (blockIdx.x - KVB64) * 64);
}

// output projection (tensor mma)
__global__ __launch_bounds__(256, 2) void oproj_kernel(
    const float* __restrict__ X, const float* __restrict__ W,
    const float* __restrict__ bias, float* __restrict__ Y)
{
    proj_mma_body64<0>(X, W, bias, Y, blockIdx.x * 64);
}

// ---------------- mma attention (register P, clamped distance-2 bias) -----
#define VS_F    4608
#define SMEM_F  8736

template<int NF>
__device__ __forceinline__ void tile_body(
    const float* __restrict__ Ksm, const float* __restrict__ Vsm,
    const float (&qreg)[4][8], float (&o)[2][4][4], float (&sums)[4],
    const float* const (&rpr)[4], float2 (&bb)[2][4], int ktile, int g, int t)
{
    const float L2E = 1.4426950408889634f;
#pragma unroll
    for (int c8 = 0; c8 < NF; c8++) {
        // consume current chunk's bias; prefetch chunk c8+2 (rolls across tiles).
        // Index CLAMPED to 0 when past NKV: load always in-bounds (clamped loads
        // only occur in the tail tile and are never consumed).
        float2 cur[4];
#pragma unroll
        for (int rr = 0; rr < 4; rr++) cur[rr] = bb[c8 & 1][rr];
        {
            int kg = ktile + 8 * (c8 + 2);
            kg = (kg < NKV) ? kg : 0;
#pragma unroll
            for (int rr = 0; rr < 4; rr++)
                bb[c8 & 1][rr] = *(const float2*)(rpr[rr] + kg + 2 * t);
        }
        // ---- S chunk = Q @ K^T ----
        const float* kp = Ksm + (8 * c8 + g) * 36 + t * 8;
        float4 k0 = *(const float4*)kp;
        float4 k1 = *(const float4*)(kp + 4);
        float kb[8] = {k0.x, k0.y, k0.z, k0.w, k1.x, k1.y, k1.z, k1.w};
        float c0[4] = {0.f, 0.f, 0.f, 0.f};
        float c1[4] = {0.f, 0.f, 0.f, 0.f};
#pragma unroll
        for (int s = 0; s < 4; s++) {
            mma8(c0, qreg[0][2*s], qreg[1][2*s], qreg[0][2*s+1], qreg[1][2*s+1],
                 kb[2*s], kb[2*s+1]);
            mma8(c1, qreg[2][2*s], qreg[3][2*s], qreg[2][2*s+1], qreg[3][2*s+1],
                 kb[2*s], kb[2*s+1]);
        }
        // ---- exp2(S + bias) -> P (registers), accumulate sums ----
        float p00 = to_tf32(ex2(fmaf(cur[0].x, L2E, c0[0])));
        float p02 = to_tf32(ex2(fmaf(cur[0].y, L2E, c0[1])));
        float p10 = to_tf32(ex2(fmaf(cur[1].x, L2E, c0[2])));
        float p12 = to_tf32(ex2(fmaf(cur[1].y, L2E, c0[3])));
        float p20 = to_tf32(ex2(fmaf(cur[2].x, L2E, c1[0])));
        float p22 = to_tf32(ex2(fmaf(cur[2].y, L2E, c1[1])));
        float p30 = to_tf32(ex2(fmaf(cur[3].x, L2E, c1[2])));
        float p32 = to_tf32(ex2(fmaf(cur[3].y, L2E, c1[3])));
        sums[0] += p00 + p02; sums[1] += p10 + p12;
        sums[2] += p20 + p22; sums[3] += p30 + p32;
        // ---- O += P @ V (A frags direct from registers) ----
        const int posw = (c8 & 1) << 1;
        const int rh   = c8 >> 1;
#pragma unroll
        for (int nf = 0; nf < 4; nf++) {
            int d  = 8 * nf + g;
            int cc = ((d << 2) + rh) ^ ((d >> 1) & 3);
            float2 bv = *(const float2*)(Vsm + t * 516 + 4 * cc + posw);
            mma8(o[0][nf], p00, p10, p02, p12, bv.x, bv.y);
            mma8(o[1][nf], p20, p30, p22, p32, bv.x, bv.y);
        }
    }
}

__global__ __launch_bounds__(128, 3) void attn_mma_kernel(
    const float* __restrict__ q, const float* __restrict__ k, const float* __restrict__ v,
    const float* __restrict__ relpos, float* __restrict__ out)
{
    __shared__ __align__(16) float dsm[SMEM_F];

    const int b   = blockIdx.z;
    const int h   = blockIdx.y;
    const int qt  = blockIdx.x;
    const int tid = threadIdx.x;
    const int lane = tid & 31, w = tid >> 5;
    const int g = lane >> 2, t = lane & 3;
    const int q0 = qt * 128;

    const float* qb = q + (size_t)(b * HEADS + h) * NQ * DH;
    const float* kb = k + (size_t)(b * HEADS + h) * NKV * DH;
    const float* vb = v + (size_t)(b * HEADS + h) * VSTRIDE;

    float qreg[4][8];
    int qraw[4];
    const float* rpr[4];
#pragma unroll
    for (int rr = 0; rr < 4; rr++) {
        int qg = q0 + 32 * w + g + 8 * rr;
        qraw[rr] = qg;
        if (qg >= NQ) qg = NQ - 1;
        const float* qp = qb + (size_t)qg * DH + t * 8;
        float4 x0 = *(const float4*)qp;
        float4 x1 = *(const float4*)(qp + 4);
        qreg[rr][0] = x0.x; qreg[rr][1] = x0.y; qreg[rr][2] = x0.z; qreg[rr][3] = x0.w;
        qreg[rr][4] = x1.x; qreg[rr][5] = x1.y; qreg[rr][6] = x1.z; qreg[rr][7] = x1.w;
        rpr[rr] = relpos + ((size_t)h * NQ + qg) * NKV;
    }

    float o[2][4][4];
#pragma unroll
    for (int i = 0; i < 2; i++)
#pragma unroll
        for (int j = 0; j < 4; j++)
#pragma unroll
            for (int c = 0; c < 4; c++) o[i][j][c] = 0.f;
    float sums[4] = {0.f, 0.f, 0.f, 0.f};

    // rolled bias prefetch state: chunks 0 and 1 of tile 0
    float2 bbuf[2][4];
#pragma unroll
    for (int rr = 0; rr < 4; rr++) {
        bbuf[0][rr] = *(const float2*)(rpr[rr] + 2 * t);
        bbuf[1][rr] = *(const float2*)(rpr[rr] + 8 + 2 * t);
    }

    const unsigned kd_base = smem_u32(dsm);
    const unsigned vd_base = smem_u32(dsm + VS_F);

    {
#pragma unroll
        for (int i = 0; i < 8; i++) {
            int idx = tid + i * 128;
            if (idx < 512) {
                int r = idx >> 3, c = idx & 7;
                cp16(kd_base + r * 144 + c * 16, kb + idx * 4);
            } else {
                int j = idx - 512;
                int dst = (j >> 7) * 129 + ((j & 127) ^ ((j >> 3) & 3));
                cp16(vd_base + dst * 16, vb + j * 4);
            }
        }
    }
    cp_commit();

    for (int tt = 0; tt < 13; tt++) {
        const int buf = tt & 1;
        cp_wait0();
        __syncthreads();

        if (tt + 1 < 13) {
            const int nb = buf ^ 1;
            const unsigned kd = kd_base + nb * 9216;
            const unsigned vd = vd_base + nb * 8256;
            const float* kg = kb + (size_t)(tt + 1) * 2048;
            const float* vg = vb + (size_t)(tt + 1) * 2048;
            if (tt + 1 < NFULL) {
#pragma unroll
                for (int i = 0; i < 8; i++) {
                    int idx = tid + i * 128;
                    if (idx < 512) {
                        int r = idx >> 3, c = idx & 7;
                        cp16(kd + r * 144 + c * 16, kg + idx * 4);
                    } else {
                        int j = idx - 512;
                        int dst = (j >> 7) * 129 + ((j & 127) ^ ((j >> 3) & 3));
                        cp16(vd + dst * 16, vg + j * 4);
                    }
                }
            } else {
#pragma unroll
                for (int i = 0; i < 2; i++) {
                    int idx = tid + i * 128;
                    if (idx < 128) {
                        int r = idx >> 3, c = idx & 7;
                        cp16(kd + r * 144 + c * 16, kg + idx * 4);
                    } else {
                        int j = idx - 128;
                        int grp = j >> 5, d = j & 31;
                        int dst = grp * 129 + ((d << 2) ^ ((d >> 1) & 3));
                        cp16(vd + dst * 16, vg + grp * 512 + d * 16);
                    }
                }
            }
        }
        cp_commit();

        const float* Ksm = dsm + buf * 2304;
        const float* Vsm = dsm + VS_F + buf * 2064;
        if (tt < NFULL)
            tile_body<8>(Ksm, Vsm, qreg, o, sums, rpr, bbuf, tt * TN, g, t);
        else
            tile_body<2>(Ksm, Vsm, qreg, o, sums, rpr, bbuf, tt * TN, g, t);
    }

    float inv[4];
#pragma unroll
    for (int rr = 0; rr < 4; rr++) {
        float s = sums[rr];
        s += __shfl_xor_sync(0xffffffffu, s, 1);
        s += __shfl_xor_sync(0xffffffffu, s, 2);
        inv[rr] = 1.f / s;
    }
#pragma unroll
    for (int mf = 0; mf < 2; mf++) {
#pragma unroll
        for (int rh = 0; rh < 2; rh++) {
            int rr = 2 * mf + rh;
            int qg = qraw[rr];
            if (qg >= NQ) continue;
            float* op = out + ((size_t)(b * NQ + qg)) * CC + h * 32 + 2 * t;
#pragma unroll
            for (int nf = 0; nf < 4; nf++) {
                float2 val = make_float2(o[mf][nf][2 * rh] * inv[rr],
                                         o[mf][nf][2 * rh + 1] * inv[rr]);
                *(float2*)(op + 8 * nf) = val;
            }
        }
    }
}

// ---------------- launch ----------------
extern "C" void kernel_launch(void* const* d_in, const int* in_sizes, int n_in,
                              void* d_out, int out_size)
{
    const float* x      = (const float*)d_in[0];
    const float* relpos = (const float*)d_in[1];
    const float* Wq     = (const float*)d_in[2];
    const float* bq     = (const float*)d_in[3];
    const float* Wk     = (const float*)d_in[4];
    const float* bk     = (const float*)d_in[5];
    const float* Wv     = (const float*)d_in[6];
    const float* bv     = (const float*)d_in[7];
    const float* cw     = (const float*)d_in[8];
    const float* cb     = (const float*)d_in[9];
    const float* gamma  = (const float*)d_in[10];
    const float* beta   = (const float*)d_in[11];
    const float* mean   = (const float*)d_in[12];
    const float* var    = (const float*)d_in[13];
    const float* Wp     = (const float*)d_in[14];
    const float* bp     = (const float*)d_in[15];
    float* out = (float*)d_out;

    float *q, *k, *v, *xr, *ao;
    cudaGetSymbolAddress((void**)&q,  g_q);
    cudaGetSymbolAddress((void**)&k,  g_k);
    cudaGetSymbolAddress((void**)&v,  g_v);
    cudaGetSymbolAddress((void**)&xr, g_xr);
    cudaGetSymbolAddress((void**)&ao, g_ao);

    // 1) fused q projection (tensor mma) + spatial-reduction conv
    int conv_blocks = (BB * NKV * CC + 255) / 256;
    qproj_conv_kernel<<<QPB64 + conv_blocks, 256>>>(x, Wq, bq, q,
                                                    cw, cb, gamma, beta, mean, var, xr);
    // 2) fused k+v projections (tensor mma; K d-permuted, V sigma-permuted)
    kvproj_kernel<<<2 * KVB64, 256>>>(xr, Wk, bk, k, Wv, bv, v);
    // 3) attention: tensor-core tf32 mma, register P, clamped distance-2 bias
    dim3 ag((NQ + 127) / 128, HEADS, BB);
    attn_mma_kernel<<<ag, 128>>>(q, k, v, relpos, ao);
    // 4) output projection (tensor mma)
    oproj_kernel<<<QPB64, 256>>>(ao, Wp, bp, out);
}

// round 13
// speedup vs baseline: 1.0961x; 1.0961x over previous
#include <cuda_runtime.h>
#include <cstdint>

// ---------------- problem constants ----------------
#define BB      8
#define HEADS   4
#define NQ      3136
#define NKV     784
#define DH      32
#define CC      128
#define TN      64                 // kv tile (12 full tiles + tail of 16)
#define NFULL   12
#define VSTRIDE 26624              // 13 tiles * 2048 floats per (b,h)
#define QPB64   ((BB * NQ) / 64)   // 392
#define KVB64   ((BB * NKV) / 64)  // 98

typedef unsigned long long u64;

// ---------------- scratch (device globals; no allocation) ----------------
__device__ float g_q [BB * HEADS * NQ  * DH];      // permuted d', tf32, scaled by 32^-.5*log2e
__device__ float g_k [BB * HEADS * NKV * DH];      // permuted d', tf32
__device__ float g_v [BB * HEADS * VSTRIDE];       // sigma-permuted Vp, tf32
__device__ float g_xr[BB * NKV * CC];
__device__ float g_ao[BB * NQ  * CC];

// ---------------- helpers ----------------
__device__ __forceinline__ float to_tf32(float x) {
    float r; asm("cvt.rna.tf32.f32 %0, %1;" : "=f"(r) : "f"(x)); return r;
}
__device__ __forceinline__ float ex2(float x) {
    float r; asm("ex2.approx.f32 %0, %1;" : "=f"(r) : "f"(x)); return r;
}
__device__ __forceinline__ unsigned smem_u32(const void* p) {
    return (unsigned)__cvta_generic_to_shared(p);
}
__device__ __forceinline__ void cp16(unsigned dst, const void* src) {
    asm volatile("cp.async.cg.shared.global [%0], [%1], 16;\n" :: "r"(dst), "l"(src));
}
__device__ __forceinline__ void cp_commit() {
    asm volatile("cp.async.commit_group;\n" ::: "memory");
}
__device__ __forceinline__ void cp_wait0() {
    asm volatile("cp.async.wait_group 0;\n" ::: "memory");
}
__device__ __forceinline__ void cp_wait1() {
    asm volatile("cp.async.wait_group 1;\n" ::: "memory");
}

// mma.sync m16n8k8 tf32 (base PTX, sm_80+)
__device__ __forceinline__ void mma8(float c[4], float a0, float a1, float a2, float a3,
                                     float b0, float b1) {
    asm volatile(
        "mma.sync.aligned.m16n8k8.row.col.f32.tf32.tf32.f32 "
        "{%0,%1,%2,%3}, {%4,%5,%6,%7}, {%8,%9}, {%0,%1,%2,%3};"
        : "+f"(c[0]), "+f"(c[1]), "+f"(c[2]), "+f"(c[3])
        : "r"(__float_as_uint(a0)), "r"(__float_as_uint(a1)),
          "r"(__float_as_uint(a2)), "r"(__float_as_uint(a3)),
          "r"(__float_as_uint(b0)), "r"(__float_as_uint(b1)));
}

// ---------------- tensor-core projection: Y = X(64x128 tile) @ W + b ------
// CTA = 64 rows x 128 cols, 8 warps (2m x 4n), warp tile 32x32,
// K chunks of 32, register-staged pipeline, XOR-swizzled Ws.
// MODE 0: plain fp32 row-major.   MODE 1: K (head-split, d-permute, tf32)
// MODE 2: Q (K-style + qscale).   MODE 4: V (head-split, sigma-permute, tf32)
template<int MODE>
__device__ __forceinline__ void proj_mma_body64(
    const float* __restrict__ X, const float* __restrict__ W,
    const float* __restrict__ bias, float* __restrict__ Y, int rowb)
{
    __shared__ __align__(16) float Xs[32 * 72];    // [k][m], pad 72
    __shared__ __align__(16) float Ws[32 * 136];   // [k][swz(perm(n))]

    const int tid  = threadIdx.x;
    const int lane = tid & 31, w = tid >> 5;
    const int g = lane >> 2, t = lane & 3;
    const int mw  = (w & 1) * 32;
    const int nwq = (w >> 1) * 32;
    const int w4  = (w >> 1) * 4;

    float o[2][4][4];
#pragma unroll
    for (int mf = 0; mf < 2; mf++)
#pragma unroll
        for (int j = 0; j < 4; j++)
#pragma unroll
            for (int c = 0; c < 4; c++) o[mf][j][c] = 0.f;

    float4 xa[2], wa[4];
    auto load_chunk = [&](int kc) {
#pragma unroll
        for (int i = 0; i < 2; i++) {
            int m = lane + 32 * i;
            xa[i] = *(const float4*)&X[(size_t)(rowb + m) * CC + kc + w * 4];
        }
#pragma unroll
        for (int i = 0; i < 4; i++) {
            int vv = tid + i * 256;
            int kk = vv >> 5, ng = vv & 31;
            wa[i] = *(const float4*)&W[(size_t)(kc + kk) * CC + ng * 4];
        }
    };

    load_chunk(0);
    for (int c = 0; c < 4; c++) {
#pragma unroll
        for (int i = 0; i < 2; i++) {
            int m = lane + 32 * i;
            float* d = &Xs[(w * 4) * 72 + m];
            d[0]   = to_tf32(xa[i].x);
            d[72]  = to_tf32(xa[i].y);
            d[144] = to_tf32(xa[i].z);
            d[216] = to_tf32(xa[i].w);
        }
#pragma unroll
        for (int i = 0; i < 4; i++) {
            int vv = tid + i * 256;
            int kk = vv >> 5, n0 = (vv & 31) * 4;
            float vals[4] = {to_tf32(wa[i].x), to_tf32(wa[i].y),
                             to_tf32(wa[i].z), to_tf32(wa[i].w)};
#pragma unroll
            for (int c2 = 0; c2 < 4; c2++) {
                int n = n0 + c2;
                int p = (n & 7) * 16 + (n >> 3);
                int sp = p ^ (((p >> 5) & 3) << 2);
                Ws[kk * 136 + sp] = vals[c2];
            }
        }
        __syncthreads();
        if (c < 3) load_chunk((c + 1) * 32);

#pragma unroll
        for (int s = 0; s < 4; s++) {
            const float* xr0 = &Xs[(s * 8 + t) * 72 + mw];
            const float* xr1 = xr0 + 4 * 72;
            float aA0 = xr0[g],      aA1 = xr0[g + 8];
            float aA2 = xr1[g],      aA3 = xr1[g + 8];
            float aB0 = xr0[g + 16], aB1 = xr0[g + 24];
            float aB2 = xr1[g + 16], aB3 = xr1[g + 24];

            int p0 = g * 16 + w4;
            int sp0 = p0 ^ (((p0 >> 5) & 3) << 2);
            const float* wr0 = &Ws[(s * 8 + t) * 136 + sp0];
            const float* wr1 = wr0 + 4 * 136;
            float4 b0 = *(const float4*)wr0;
            float4 b1 = *(const float4*)wr1;
            float bb0[4] = {b0.x, b0.y, b0.z, b0.w};
            float bb1[4] = {b1.x, b1.y, b1.z, b1.w};
#pragma unroll
            for (int j = 0; j < 4; j++) {
                mma8(o[0][j], aA0, aA1, aA2, aA3, bb0[j], bb1[j]);
                mma8(o[1][j], aB0, aB1, aB2, aB3, bb0[j], bb1[j]);
            }
        }
        __syncthreads();
    }

    const float qscale = 0.25503486f;   // 32^-0.5 * log2(e)
#pragma unroll
    for (int j = 0; j < 4; j++) {
        int col = nwq + 8 * j + 2 * t;
        if (MODE == 0) {
            float2 bv = *(const float2*)&bias[col];
#pragma unroll
            for (int mf = 0; mf < 2; mf++) {
                int r0 = rowb + mw + 16 * mf + g;
                *(float2*)&Y[(size_t)r0 * CC + col] =
                    make_float2(o[mf][j][0] + bv.x, o[mf][j][1] + bv.y);
                *(float2*)&Y[(size_t)(r0 + 8) * CC + col] =
                    make_float2(o[mf][j][2] + bv.x, o[mf][j][3] + bv.y);
            }
        } else {
            int h = col >> 5;
            int d0 = col & 31, d1 = d0 + 1;
            float bx = bias[col], by = bias[col + 1];
#pragma unroll
            for (int mf = 0; mf < 2; mf++) {
#pragma unroll
                for (int rh = 0; rh < 2; rh++) {
                    int row = rowb + mw + 16 * mf + g + 8 * rh;
                    float v0 = o[mf][j][2 * rh]     + bx;
                    float v1 = o[mf][j][2 * rh + 1] + by;
                    if (MODE == 2) { v0 *= qscale; v1 *= qscale; }
                    if (MODE == 4) {
                        int b = row / NKV, n = row % NKV;
                        int tile = n >> 6, rr = n & 63;
                        int off = ((rr & 7) >> 1) * 512 + 2 * (rr >> 3) + (rr & 1);
                        float* bp = &Y[(size_t)(b * HEADS + h) * VSTRIDE
                                       + tile * 2048 + off];
                        bp[d0 * 16] = to_tf32(v0);
                        bp[d1 * 16] = to_tf32(v1);
                    } else {
                        const int RPB = (MODE == 2) ? NQ : NKV;
                        int b = row / RPB, n = row % RPB;
                        int dp0 = (d0 & 3) * 8 + (d0 >> 2);
                        int dp1 = (d1 & 3) * 8 + (d1 >> 2);
                        float* bp = &Y[((size_t)(b * HEADS + h) * RPB + n) * DH];
                        bp[dp0] = to_tf32(v0);
                        bp[dp1] = to_tf32(v1);
                    }
                }
            }
        }
    }
}

// fused: q projection (tensor) + spatial-reduction conv
__global__ __launch_bounds__(256, 2) void qproj_conv_kernel(
    const float* __restrict__ x,
    const float* __restrict__ Wq, const float* __restrict__ bq, float* __restrict__ Q,
    const float* __restrict__ cw, const float* __restrict__ cb,
    const float* __restrict__ gamma, const float* __restrict__ beta,
    const float* __restrict__ mean, const float* __restrict__ var,
    float* __restrict__ xr)
{
    if (blockIdx.x < QPB64) {
        proj_mma_body64<2>(x, Wq, bq, Q, blockIdx.x * 64);
        return;
    }
    int t = (blockIdx.x - QPB64) * 256 + threadIdx.x;
    if (t >= BB * NKV * CC) return;
    int c = t & (CC - 1);
    int p = (t >> 7) % NKV;
    int b = t / (NKV * CC);
    int oy = p / 28, ox = p % 28;

    const float* xb = x + (size_t)b * NQ * CC;
    float s = 0.f;
#pragma unroll
    for (int i = 0; i < 2; i++)
#pragma unroll
        for (int j = 0; j < 2; j++)
            s += xb[(size_t)((2 * oy + i) * 56 + (2 * ox + j)) * CC + c] * cw[c * 4 + i * 2 + j];
    s += cb[c];
    float iv = gamma[c] * rsqrtf(var[c] + 1e-5f);
    xr[t] = s * iv + (beta[c] - mean[c] * iv);
}

// fused k+v projections (tensor mma)
__global__ __launch_bounds__(256, 2) void kvproj_kernel(
    const float* __restrict__ X,
    const float* __restrict__ Wk, const float* __restrict__ bk, float* __restrict__ K,
    const float* __restrict__ Wv, const float* __restrict__ bv, float* __restrict__ V)
{
    if (blockIdx.x < KVB64)
        proj_mma_body64<1>(X, Wk, bk, K, blockIdx.x * 64);
    else
        proj_mma_body64<4>(X, Wv, bv, V, (blockIdx.x - KVB64) * 64);
}

// output projection (tensor mma)
__global__ __launch_bounds__(256, 2) void oproj_kernel(
    const float* __restrict__ X, const float* __restrict__ W,
    const float* __restrict__ bias, float* __restrict__ Y)
{
    proj_mma_body64<0>(X, W, bias, Y, blockIdx.x * 64);
}

// ---------------- mma attention (register P, smem-staged coalesced bias) --
// dynamic smem layout (floats):
//   [0, 4608)        K double buffer (2 x 64 x 36)
//   [4608, 8736)     V double buffer (2 x 4 x 516)
//   [8736, 17952)    bias double buffer (2 x 128 x 36), half-tile (32 kv) each
#define VS_F    4608
#define BS_F    8736
#define SMEM_ATTN_F   17952
#define SMEM_ATTN_B   (SMEM_ATTN_F * 4)

// NC chunks of 8 kv; c8base = chunk offset within the 64-kv tile (for V layout).
// Bias for these chunks comes from Bsm (cols = 8*cc + 2t within the half).
template<int NC>
__device__ __forceinline__ void half_body(
    const float* __restrict__ Ksm, const float* __restrict__ Vsm,
    const float* __restrict__ Bsm,
    const float (&qreg)[4][8], float (&o)[2][4][4], float (&sums)[4],
    int c8base, int g, int t, int w)
{
    const float L2E = 1.4426950408889634f;
#pragma unroll
    for (int cc = 0; cc < NC; cc++) {
        const int c8 = c8base + cc;
        // ---- bias from smem (LDS.64, row stride 36) ----
        float2 cur[4];
#pragma unroll
        for (int rr = 0; rr < 4; rr++)
            cur[rr] = *(const float2*)(Bsm + (32 * w + 8 * rr + g) * 36 + 8 * cc + 2 * t);
        // ---- S chunk = Q @ K^T ----
        const float* kp = Ksm + (8 * c8 + g) * 36 + t * 8;
        float4 k0 = *(const float4*)kp;
        float4 k1 = *(const float4*)(kp + 4);
        float kb[8] = {k0.x, k0.y, k0.z, k0.w, k1.x, k1.y, k1.z, k1.w};
        float c0[4] = {0.f, 0.f, 0.f, 0.f};
        float c1[4] = {0.f, 0.f, 0.f, 0.f};
#pragma unroll
        for (int s = 0; s < 4; s++) {
            mma8(c0, qreg[0][2*s], qreg[1][2*s], qreg[0][2*s+1], qreg[1][2*s+1],
                 kb[2*s], kb[2*s+1]);
            mma8(c1, qreg[2][2*s], qreg[3][2*s], qreg[2][2*s+1], qreg[3][2*s+1],
                 kb[2*s], kb[2*s+1]);
        }
        // ---- exp2(S + bias) -> P (registers), accumulate sums ----
        float p00 = to_tf32(ex2(fmaf(cur[0].x, L2E, c0[0])));
        float p02 = to_tf32(ex2(fmaf(cur[0].y, L2E, c0[1])));
        float p10 = to_tf32(ex2(fmaf(cur[1].x, L2E, c0[2])));
        float p12 = to_tf32(ex2(fmaf(cur[1].y, L2E, c0[3])));
        float p20 = to_tf32(ex2(fmaf(cur[2].x, L2E, c1[0])));
        float p22 = to_tf32(ex2(fmaf(cur[2].y, L2E, c1[1])));
        float p30 = to_tf32(ex2(fmaf(cur[3].x, L2E, c1[2])));
        float p32 = to_tf32(ex2(fmaf(cur[3].y, L2E, c1[3])));
        sums[0] += p00 + p02; sums[1] += p10 + p12;
        sums[2] += p20 + p22; sums[3] += p30 + p32;
        // ---- O += P @ V (A frags direct from registers) ----
        const int posw = (c8 & 1) << 1;
        const int rh   = c8 >> 1;
#pragma unroll
        for (int nf = 0; nf < 4; nf++) {
            int d  = 8 * nf + g;
            int cv = ((d << 2) + rh) ^ ((d >> 1) & 3);
            float2 bv = *(const float2*)(Vsm + t * 516 + 4 * cv + posw);
            mma8(o[0][nf], p00, p10, p02, p12, bv.x, bv.y);
            mma8(o[1][nf], p20, p30, p22, p32, bv.x, bv.y);
        }
    }
}

__global__ __launch_bounds__(128, 3) void attn_mma_kernel(
    const float* __restrict__ q, const float* __restrict__ k, const float* __restrict__ v,
    const float* __restrict__ relpos, float* __restrict__ out)
{
    extern __shared__ __align__(16) float dsm[];

    const int b   = blockIdx.z;
    const int h   = blockIdx.y;
    const int qt  = blockIdx.x;
    const int tid = threadIdx.x;
    const int lane = tid & 31, w = tid >> 5;
    const int g = lane >> 2, t = lane & 3;
    const int q0 = qt * 128;

    const float* qb = q + (size_t)(b * HEADS + h) * NQ * DH;
    const float* kb = k + (size_t)(b * HEADS + h) * NKV * DH;
    const float* vb = v + (size_t)(b * HEADS + h) * VSTRIDE;
    const float* rpb = relpos + (size_t)h * NQ * NKV;

    float qreg[4][8];
    int qraw[4];
#pragma unroll
    for (int rr = 0; rr < 4; rr++) {
        int qg = q0 + 32 * w + g + 8 * rr;
        qraw[rr] = qg;
        if (qg >= NQ) qg = NQ - 1;
        const float* qp = qb + (size_t)qg * DH + t * 8;
        float4 x0 = *(const float4*)qp;
        float4 x1 = *(const float4*)(qp + 4);
        qreg[rr][0] = x0.x; qreg[rr][1] = x0.y; qreg[rr][2] = x0.z; qreg[rr][3] = x0.w;
        qreg[rr][4] = x1.x; qreg[rr][5] = x1.y; qreg[rr][6] = x1.z; qreg[rr][7] = x1.w;
    }

    float o[2][4][4];
#pragma unroll
    for (int i = 0; i < 2; i++)
#pragma unroll
        for (int j = 0; j < 4; j++)
#pragma unroll
            for (int c = 0; c < 4; c++) o[i][j][c] = 0.f;
    float sums[4] = {0.f, 0.f, 0.f, 0.f};

    const unsigned kd_base = smem_u32(dsm);
    const unsigned vd_base = smem_u32(dsm + VS_F);
    const unsigned bd_base = smem_u32(dsm + BS_F);

    // coalesced bias stage: 128 rows x 32 kv cols into [128][36] buffer.
    // clamped (never guarded) addresses -> always in-bounds.
    auto stage_bias = [&](unsigned bdst, int kcol) {
#pragma unroll
        for (int i = 0; i < 8; i++) {
            int G = tid + i * 128;
            int r = G >> 3, c = G & 7;
            int row = q0 + r; row = (row < NQ) ? row : (NQ - 1);
            int col = kcol + c * 4; col = (col <= NKV - 4) ? col : (NKV - 4);
            cp16(bdst + r * 144 + c * 16, rpb + (size_t)row * NKV + col);
        }
    };

    // ---- prologue: KV tile 0 + bias half0 of tile 0 ----
    {
#pragma unroll
        for (int i = 0; i < 8; i++) {
            int idx = tid + i * 128;
            if (idx < 512) {
                int r = idx >> 3, c = idx & 7;
                cp16(kd_base + r * 144 + c * 16, kb + idx * 4);
            } else {
                int j = idx - 512;
                int dst = (j >> 7) * 129 + ((j & 127) ^ ((j >> 3) & 3));
                cp16(vd_base + dst * 16, vb + j * 4);
            }
        }
    }
    cp_commit();
    stage_bias(bd_base, 0);
    cp_commit();

    for (int tt = 0; tt < 13; tt++) {
        const int buf = tt & 1;
        cp_wait0();
        __syncthreads();

        const float* Ksm = dsm + buf * 2304;
        const float* Vsm = dsm + VS_F + buf * 2064;
        const float* BsA = dsm + BS_F;
        const float* BsB = dsm + BS_F + 4608;

        if (tt < NFULL) {
            // stage bias half1 of this tile (group A)
            stage_bias(bd_base + 4608 * 4, tt * TN + 32);
            cp_commit();
            // prefetch next KV tile (group B)
            {
                const int nb = buf ^ 1;
                const unsigned kd = kd_base + nb * 9216;
                const unsigned vd = vd_base + nb * 8256;
                const float* kg = kb + (size_t)(tt + 1) * 2048;
                const float* vg = vb + (size_t)(tt + 1) * 2048;
                if (tt + 1 < NFULL) {
#pragma unroll
                    for (int i = 0; i < 8; i++) {
                        int idx = tid + i * 128;
                        if (idx < 512) {
                            int r = idx >> 3, c = idx & 7;
                            cp16(kd + r * 144 + c * 16, kg + idx * 4);
                        } else {
                            int j = idx - 512;
                            int dst = (j >> 7) * 129 + ((j & 127) ^ ((j >> 3) & 3));
                            cp16(vd + dst * 16, vg + j * 4);
                        }
                    }
                } else {
                    // tail tile: 16 kv rows -> 128 K-chunks + 128 V-chunks
#pragma unroll
                    for (int i = 0; i < 2; i++) {
                        int idx = tid + i * 128;
                        if (idx < 128) {
                            int r = idx >> 3, c = idx & 7;
                            cp16(kd + r * 144 + c * 16, kg + idx * 4);
                        } else {
                            int j = idx - 128;
                            int grp = j >> 5, d = j & 31;
                            int dst = grp * 129 + ((d << 2) ^ ((d >> 1) & 3));
                            cp16(vd + dst * 16, vg + grp * 512 + d * 16);
                        }
                    }
                }
            }
            cp_commit();

            // chunks 0..3 consume bias buffer A
            half_body<4>(Ksm, Vsm, BsA, qreg, o, sums, 0, g, t, w);

            cp_wait1();          // bias half1 (group A) done; KV still in flight
            __syncthreads();

            // stage bias half0 of next tile into buffer A (group C)
            stage_bias(bd_base, (tt + 1) * TN);
            cp_commit();

            // chunks 4..7 consume bias buffer B
            half_body<4>(Ksm, Vsm, BsB, qreg, o, sums, 4, g, t, w);
        } else {
            // tail tile: 2 chunks, bias buffer A (staged at tile 11 mid)
            half_body<2>(Ksm, Vsm, BsA, qreg, o, sums, 0, g, t, w);
        }
    }

    float inv[4];
#pragma unroll
    for (int rr = 0; rr < 4; rr++) {
        float s = sums[rr];
        s += __shfl_xor_sync(0xffffffffu, s, 1);
        s += __shfl_xor_sync(0xffffffffu, s, 2);
        inv[rr] = 1.f / s;
    }
#pragma unroll
    for (int mf = 0; mf < 2; mf++) {
#pragma unroll
        for (int rh = 0; rh < 2; rh++) {
            int rr = 2 * mf + rh;
            int qg = qraw[rr];
            if (qg >= NQ) continue;
            float* op = out + ((size_t)(b * NQ + qg)) * CC + h * 32 + 2 * t;
#pragma unroll
            for (int nf = 0; nf < 4; nf++) {
                float2 val = make_float2(o[mf][nf][2 * rh] * inv[rr],
                                         o[mf][nf][2 * rh + 1] * inv[rr]);
                *(float2*)(op + 8 * nf) = val;
            }
        }
    }
}

// ---------------- launch ----------------
extern "C" void kernel_launch(void* const* d_in, const int* in_sizes, int n_in,
                              void* d_out, int out_size)
{
    const float* x      = (const float*)d_in[0];
    const float* relpos = (const float*)d_in[1];
    const float* Wq     = (const float*)d_in[2];
    const float* bq     = (const float*)d_in[3];
    const float* Wk     = (const float*)d_in[4];
    const float* bk     = (const float*)d_in[5];
    const float* Wv     = (const float*)d_in[6];
    const float* bv     = (const float*)d_in[7];
    const float* cw     = (const float*)d_in[8];
    const float* cb     = (const float*)d_in[9];
    const float* gamma  = (const float*)d_in[10];
    const float* beta   = (const float*)d_in[11];
    const float* mean   = (const float*)d_in[12];
    const float* var    = (const float*)d_in[13];
    const float* Wp     = (const float*)d_in[14];
    const float* bp     = (const float*)d_in[15];
    float* out = (float*)d_out;

    float *q, *k, *v, *xr, *ao;
    cudaGetSymbolAddress((void**)&q,  g_q);
    cudaGetSymbolAddress((void**)&k,  g_k);
    cudaGetSymbolAddress((void**)&v,  g_v);
    cudaGetSymbolAddress((void**)&xr, g_xr);
    cudaGetSymbolAddress((void**)&ao, g_ao);

    cudaFuncSetAttribute(attn_mma_kernel,
                         cudaFuncAttributeMaxDynamicSharedMemorySize, SMEM_ATTN_B);

    // 1) fused q projection (tensor mma) + spatial-reduction conv
    int conv_blocks = (BB * NKV * CC + 255) / 256;
    qproj_conv_kernel<<<QPB64 + conv_blocks, 256>>>(x, Wq, bq, q,
                                                    cw, cb, gamma, beta, mean, var, xr);
    // 2) fused k+v projections (tensor mma; K d-permuted, V sigma-permuted)
    kvproj_kernel<<<2 * KVB64, 256>>>(xr, Wk, bk, k, Wv, bv, v);
    // 3) attention: tensor-core tf32 mma, register P, smem-staged coalesced bias
    dim3 ag((NQ + 127) / 128, HEADS, BB);
    attn_mma_kernel<<<ag, 128, SMEM_ATTN_B>>>(q, k, v, relpos, ao);
    // 4) output projection (tensor mma)
    oproj_kernel<<<QPB64, 256>>>(ao, Wp, bp, out);
}